// round 6
// baseline (speedup 1.0000x reference)
#include <cuda_runtime.h>
#include <cuda_bf16.h>
#include <cstdint>

// Problem constants (B=2, T=512, C=256, HID=1024)
constexpr int Mrows = 1024;   // B*T
constexpr int Cdim  = 256;
constexpr int Hdim  = 1024;

// Static device scratch: only the hidden activation survives between kernels.
__device__ __nv_bfloat16 g_hid[Mrows * Hdim];

// ---------------------------------------------------------------------------
// PTX helpers
// ---------------------------------------------------------------------------
__device__ __forceinline__ uint32_t smem_u32(const void* p) {
    return (uint32_t)__cvta_generic_to_shared(p);
}
__device__ __forceinline__ void ldsm_x4(uint32_t& r0, uint32_t& r1,
                                        uint32_t& r2, uint32_t& r3, uint32_t a) {
    asm volatile("ldmatrix.sync.aligned.m8n8.x4.shared.b16 {%0,%1,%2,%3},[%4];"
                 : "=r"(r0), "=r"(r1), "=r"(r2), "=r"(r3) : "r"(a));
}
__device__ __forceinline__ void ldsm_x2(uint32_t& r0, uint32_t& r1, uint32_t a) {
    asm volatile("ldmatrix.sync.aligned.m8n8.x2.shared.b16 {%0,%1},[%2];"
                 : "=r"(r0), "=r"(r1) : "r"(a));
}
__device__ __forceinline__ void mma_bf16(float* c, const uint32_t* a, const uint32_t* b) {
    asm volatile(
        "mma.sync.aligned.m16n8k16.row.col.f32.bf16.bf16.f32 "
        "{%0,%1,%2,%3},{%4,%5,%6,%7},{%8,%9},{%0,%1,%2,%3};"
        : "+f"(c[0]), "+f"(c[1]), "+f"(c[2]), "+f"(c[3])
        : "r"(a[0]), "r"(a[1]), "r"(a[2]), "r"(a[3]), "r"(b[0]), "r"(b[1]));
}
__device__ __forceinline__ void cp_async16(uint32_t s, const void* g) {
    asm volatile("cp.async.cg.shared.global [%0], [%1], 16;" :: "r"(s), "l"(g));
}
__device__ __forceinline__ void cp_commit() {
    asm volatile("cp.async.commit_group;");
}
template <int N> __device__ __forceinline__ void cp_wait() {
    asm volatile("cp.async.wait_group %0;" :: "n"(N));
}

// Convert 32 consecutive fp32 (8 float4 loads) -> 32 bf16, store as 4 uint4.
__device__ __forceinline__ void cvt_store32(const float* __restrict__ src,
                                            __nv_bfloat16* __restrict__ dst) {
    float4 f[8];
    #pragma unroll
    for (int i = 0; i < 8; i++)
        f[i] = *reinterpret_cast<const float4*>(src + i * 4);
    __nv_bfloat162 h[16];
    #pragma unroll
    for (int i = 0; i < 8; i++) {
        h[2*i].x   = __float2bfloat16(f[i].x);
        h[2*i].y   = __float2bfloat16(f[i].y);
        h[2*i+1].x = __float2bfloat16(f[i].z);
        h[2*i+1].y = __float2bfloat16(f[i].w);
    }
    #pragma unroll
    for (int i = 0; i < 4; i++)
        *reinterpret_cast<uint4*>(dst + i * 8) =
            *reinterpret_cast<uint4*>(&h[4*i]);
}

// ===========================================================================
// Kernel 1: fused  LN(x+bp)  +  W1 fp32->bf16 convert  +  GEMM1 + relu
//   hid = relu( LN(x+bp) @ W1^T + bf1 )   M=1024 N=1024 K=256
// grid (8 n-tiles, 16 m-tiles), 256 threads. BM=64 BN=128 K=256 (resident).
// ===========================================================================
__global__ void __launch_bounds__(256, 1)
fused_ln_gemm1(const float* __restrict__ x,
               const float* __restrict__ bp,
               const float* __restrict__ g2,
               const float* __restrict__ b2,
               const float* __restrict__ W1,
               const float* __restrict__ bf1)
{
    constexpr int BM = 64, BN = 128, K = 256;
    constexpr int LDS = K + 8;                       // 264 (row stride mod 128B = 16B)
    extern __shared__ char smem[];
    __nv_bfloat16* As = reinterpret_cast<__nv_bfloat16*>(smem);                 // 64*264
    __nv_bfloat16* Bs = reinterpret_cast<__nv_bfloat16*>(smem) + BM * LDS;      // 128*264

    const int tid  = threadIdx.x;
    const int lane = tid & 31;
    const int warp = tid >> 5;
    const int m0   = blockIdx.y * BM;
    const int n0   = blockIdx.x * BN;

    // ---- W1 convert: thread t -> row n = t>>1, k half = (t&1)*128, 4 chunks of 32
    {
        const int n  = tid >> 1;
        const int kb = (tid & 1) * 128;
        #pragma unroll
        for (int c = 0; c < 4; c++) {
            const int k = kb + c * 32;
            cvt_store32(&W1[(size_t)(n0 + n) * K + k], &Bs[n * LDS + k]);
        }
    }

    // ---- LN: warp w handles rows w*8 .. w*8+7 ; lane covers 8 columns
    {
        const int c0 = lane * 8;
        const float4 pa = __ldg((const float4*)(bp + c0));
        const float4 pb = __ldg((const float4*)(bp + c0 + 4));
        const float4 ga = __ldg((const float4*)(g2 + c0));
        const float4 gb = __ldg((const float4*)(g2 + c0 + 4));
        const float4 ba = __ldg((const float4*)(b2 + c0));
        const float4 bb = __ldg((const float4*)(b2 + c0 + 4));
        const float gg[8]  = {ga.x, ga.y, ga.z, ga.w, gb.x, gb.y, gb.z, gb.w};
        const float bbv[8] = {ba.x, ba.y, ba.z, ba.w, bb.x, bb.y, bb.z, bb.w};
        const float pp[8]  = {pa.x, pa.y, pa.z, pa.w, pb.x, pb.y, pb.z, pb.w};

        #pragma unroll
        for (int r = 0; r < 8; r++) {
            const int row = warp * 8 + r;
            const float* rp = x + (size_t)(m0 + row) * Cdim + c0;
            const float4 a = __ldg((const float4*)rp);
            const float4 b = __ldg((const float4*)(rp + 4));
            float v[8] = {a.x + pp[0], a.y + pp[1], a.z + pp[2], a.w + pp[3],
                          b.x + pp[4], b.y + pp[5], b.z + pp[6], b.w + pp[7]};
            float s = 0.f, q = 0.f;
            #pragma unroll
            for (int j = 0; j < 8; j++) { s += v[j]; q += v[j] * v[j]; }
            #pragma unroll
            for (int o = 16; o > 0; o >>= 1) {
                s += __shfl_xor_sync(0xffffffffu, s, o);
                q += __shfl_xor_sync(0xffffffffu, q, o);
            }
            const float mean = s * (1.0f / Cdim);
            const float var  = q * (1.0f / Cdim) - mean * mean;
            const float inv  = rsqrtf(var + 1e-5f);
            __nv_bfloat162 o2[4];
            #pragma unroll
            for (int j = 0; j < 4; j++) {
                o2[j].x = __float2bfloat16((v[2*j]   - mean) * inv * gg[2*j]   + bbv[2*j]);
                o2[j].y = __float2bfloat16((v[2*j+1] - mean) * inv * gg[2*j+1] + bbv[2*j+1]);
            }
            *reinterpret_cast<uint4*>(&As[row * LDS + c0]) =
                *reinterpret_cast<uint4*>(o2);
        }
    }
    __syncthreads();   // As + Bs fully resident

    // ---- Mainloop: whole K in smem, zero further barriers
    constexpr int WARPS_N = 4;           // 2x4 warps; WM=32, WN=32
    constexpr int MT = 2, NTt = 4;
    const int wm = warp / WARPS_N;
    const int wn = warp % WARPS_N;

    float acc[MT][NTt][4];
    #pragma unroll
    for (int i = 0; i < MT; i++)
        #pragma unroll
        for (int j = 0; j < NTt; j++)
            #pragma unroll
            for (int r = 0; r < 4; r++) acc[i][j][r] = 0.f;

    #pragma unroll
    for (int ks = 0; ks < K; ks += 16) {
        uint32_t afrag[MT][4];
        #pragma unroll
        for (int mt = 0; mt < MT; mt++) {
            const int row = wm * 32 + mt * 16 + (lane & 15);
            const int col = ks + (lane >> 4) * 8;
            ldsm_x4(afrag[mt][0], afrag[mt][1], afrag[mt][2], afrag[mt][3],
                    smem_u32(&As[row * LDS + col]));
        }
        uint32_t bfrag[NTt][2];
        #pragma unroll
        for (int nt = 0; nt < NTt; nt++) {
            const int row = wn * 32 + nt * 8 + (lane & 7);
            const int col = ks + ((lane >> 3) & 1) * 8;
            ldsm_x2(bfrag[nt][0], bfrag[nt][1], smem_u32(&Bs[row * LDS + col]));
        }
        #pragma unroll
        for (int mt = 0; mt < MT; mt++)
            #pragma unroll
            for (int nt = 0; nt < NTt; nt++)
                mma_bf16(acc[mt][nt], afrag[mt], bfrag[nt]);
    }

    // ---- Epilogue: relu(acc + bf1) -> bf16 g_hid
    #pragma unroll
    for (int mt = 0; mt < MT; mt++) {
        #pragma unroll
        for (int nt = 0; nt < NTt; nt++) {
            const int m = m0 + wm * 32 + mt * 16 + (lane >> 2);
            const int n = n0 + wn * 32 + nt * 8 + (lane & 3) * 2;
            const float b0 = __ldg(bf1 + n), b1 = __ldg(bf1 + n + 1);
            float c0 = fmaxf(acc[mt][nt][0] + b0, 0.f);
            float c1 = fmaxf(acc[mt][nt][1] + b1, 0.f);
            float c2 = fmaxf(acc[mt][nt][2] + b0, 0.f);
            float c3 = fmaxf(acc[mt][nt][3] + b1, 0.f);
            __nv_bfloat162 p;
            p.x = __float2bfloat16(c0); p.y = __float2bfloat16(c1);
            *reinterpret_cast<__nv_bfloat162*>(&g_hid[(size_t)m * Hdim + n]) = p;
            p.x = __float2bfloat16(c2); p.y = __float2bfloat16(c3);
            *reinterpret_cast<__nv_bfloat162*>(&g_hid[(size_t)(m + 8) * Hdim + n]) = p;
        }
    }
}

// ===========================================================================
// Kernel 2: fused  W2 convert + GEMM2 + residual
//   out = hid @ W2^T + x + bp + bf2     M=1024 N=256 K=1024
// grid (8 n-tiles, 16 m-tiles), 256 threads. BM=64 BN=32, all K resident.
// A loaded via 8 up-front cp.async stages; W2 converted while they fly.
// ===========================================================================
__global__ void __launch_bounds__(256, 1)
fused_gemm2(const float* __restrict__ W2,
            const float* __restrict__ x,
            const float* __restrict__ bp,
            const float* __restrict__ bf2,
            float* __restrict__ out)
{
    constexpr int BM = 64, BN = 32, K = 1024;
    constexpr int LDS = K + 8;                        // 1032 (stride mod 128B = 16B)
    constexpr int NSTAGE = 8, BK = K / NSTAGE;        // 128
    extern __shared__ char smem[];
    __nv_bfloat16* As = reinterpret_cast<__nv_bfloat16*>(smem);                // 64*1032
    __nv_bfloat16* Bs = reinterpret_cast<__nv_bfloat16*>(smem) + BM * LDS;     // 32*1032

    const int tid  = threadIdx.x;
    const int lane = tid & 31;
    const int warp = tid >> 5;
    const int m0   = blockIdx.y * BM;
    const int n0   = blockIdx.x * BN;

    // ---- Issue ALL 8 A-stages up front (one commit group each, max MLP)
    #pragma unroll
    for (int s = 0; s < NSTAGE; s++) {
        #pragma unroll
        for (int j = 0; j < 4; j++) {                       // 1024 cp16 / 256 thr
            const int idx = tid + j * 256;
            const int r  = idx >> 4;                        // 16 cp16 per row
            const int cv = idx & 15;
            cp_async16(smem_u32(&As[r * LDS + s * BK + cv * 8]),
                       &g_hid[(size_t)(m0 + r) * K + s * BK + cv * 8]);
        }
        cp_commit();
    }

    // ---- W2 convert while A flies: thread t -> row n = t>>3, k base (t&7)*128
    {
        const int n  = tid >> 3;
        const int kb = (tid & 7) * 128;
        #pragma unroll
        for (int c = 0; c < 4; c++) {
            const int k = kb + c * 32;
            cvt_store32(&W2[(size_t)(n0 + n) * K + k], &Bs[n * LDS + k]);
        }
    }

    // ---- Warp tiling: 4x2 warps; WM=16, WN=16 -> MT=1, NTt=2
    constexpr int NTt = 2;
    const int wm = warp >> 1;
    const int wn = warp & 1;

    float acc[NTt][4] = {};

    #pragma unroll
    for (int s = 0; s < NSTAGE; s++) {
        switch (s) {                                   // compile-time after unroll
            case 0: cp_wait<7>(); break;  case 1: cp_wait<6>(); break;
            case 2: cp_wait<5>(); break;  case 3: cp_wait<4>(); break;
            case 4: cp_wait<3>(); break;  case 5: cp_wait<2>(); break;
            case 6: cp_wait<1>(); break;  default: cp_wait<0>(); break;
        }
        __syncthreads();   // stage-s A visible to all warps (Bs covered by s=0)

        #pragma unroll
        for (int k16 = 0; k16 < BK; k16 += 16) {
            const int ks = s * BK + k16;
            uint32_t afrag[4];
            {
                const int row = wm * 16 + (lane & 15);
                const int col = ks + (lane >> 4) * 8;
                ldsm_x4(afrag[0], afrag[1], afrag[2], afrag[3],
                        smem_u32(&As[row * LDS + col]));
            }
            uint32_t bfrag[NTt][2];
            #pragma unroll
            for (int nt = 0; nt < NTt; nt++) {
                const int row = wn * 16 + nt * 8 + (lane & 7);
                const int col = ks + ((lane >> 3) & 1) * 8;
                ldsm_x2(bfrag[nt][0], bfrag[nt][1], smem_u32(&Bs[row * LDS + col]));
            }
            #pragma unroll
            for (int nt = 0; nt < NTt; nt++)
                mma_bf16(acc[nt], afrag, bfrag[nt]);
        }
    }

    // ---- Epilogue: acc + x + bp + bf2 -> fp32 out
    #pragma unroll
    for (int nt = 0; nt < NTt; nt++) {
        const int m = m0 + wm * 16 + (lane >> 2);
        const int n = n0 + wn * 16 + nt * 8 + (lane & 3) * 2;
        const float b0 = __ldg(bp + n) + __ldg(bf2 + n);
        const float b1 = __ldg(bp + n + 1) + __ldg(bf2 + n + 1);
        const float2 r0 = __ldg((const float2*)&x[(size_t)m * Cdim + n]);
        const float2 r1 = __ldg((const float2*)&x[(size_t)(m + 8) * Cdim + n]);
        float2 p;
        p.x = acc[nt][0] + r0.x + b0; p.y = acc[nt][1] + r0.y + b1;
        *reinterpret_cast<float2*>(&out[(size_t)m * Cdim + n]) = p;
        p.x = acc[nt][2] + r1.x + b0; p.y = acc[nt][3] + r1.y + b1;
        *reinterpret_cast<float2*>(&out[(size_t)(m + 8) * Cdim + n]) = p;
    }
}

// ---------------------------------------------------------------------------
// Attention branch is exactly 0 (transform *= 0.0)  =>  sa == bp.
//   y = (x + bp) + relu(LN(x+bp)@W1^T + bf1) @ W2^T + bf2
// Inputs: 0:x 1:Wt 2:Wp 3:bp 4:g1 5:b1 6:g2 7:b2 8:W1 9:bf1 10:W2 11:bf2
// ---------------------------------------------------------------------------
extern "C" void kernel_launch(void* const* d_in, const int* in_sizes, int n_in,
                              void* d_out, int out_size)
{
    const float* x   = (const float*)d_in[0];
    const float* bp  = (const float*)d_in[3];
    const float* g2  = (const float*)d_in[6];
    const float* b2  = (const float*)d_in[7];
    const float* W1  = (const float*)d_in[8];
    const float* bf1 = (const float*)d_in[9];
    const float* W2  = (const float*)d_in[10];
    const float* bf2 = (const float*)d_in[11];
    float* out = (float*)d_out;

    constexpr int SMEM1 = (64 + 128) * 264 * 2;     // 101376 B
    constexpr int SMEM2 = (64 + 32) * 1032 * 2;     // 198144 B
    cudaFuncSetAttribute(fused_ln_gemm1,
                         cudaFuncAttributeMaxDynamicSharedMemorySize, SMEM1);
    cudaFuncSetAttribute(fused_gemm2,
                         cudaFuncAttributeMaxDynamicSharedMemorySize, SMEM2);

    // 1) hid = relu(LN(x+bp) @ W1^T + bf1)   grid 8x16
    fused_ln_gemm1<<<dim3(Hdim / 128, Mrows / 64), 256, SMEM1>>>(
        x, bp, g2, b2, W1, bf1);

    // 2) out = hid @ W2^T + x + bp + bf2     grid 8x16
    fused_gemm2<<<dim3(Cdim / 32, Mrows / 64), 256, SMEM2>>>(
        W2, x, bp, bf2, out);
}

// round 7
// speedup vs baseline: 1.3412x; 1.3412x over previous
#include <cuda_runtime.h>
#include <cuda_bf16.h>
#include <cstdint>

// Problem constants (B=2, T=512, C=256, HID=1024)
constexpr int Mrows = 1024;   // B*T
constexpr int Cdim  = 256;
constexpr int Hdim  = 1024;

// Static device scratch
__device__ __nv_bfloat16 g_h2 [Mrows * Cdim];
__device__ __nv_bfloat16 g_hid[Mrows * Hdim];
__device__ __nv_bfloat16 g_W1 [Hdim * Cdim];
__device__ __nv_bfloat16 g_W2 [Cdim * Hdim];

// ---------------------------------------------------------------------------
// PTX helpers
// ---------------------------------------------------------------------------
__device__ __forceinline__ uint32_t smem_u32(const void* p) {
    return (uint32_t)__cvta_generic_to_shared(p);
}
__device__ __forceinline__ void ldsm_x4(uint32_t& r0, uint32_t& r1,
                                        uint32_t& r2, uint32_t& r3, uint32_t a) {
    asm volatile("ldmatrix.sync.aligned.m8n8.x4.shared.b16 {%0,%1,%2,%3},[%4];"
                 : "=r"(r0), "=r"(r1), "=r"(r2), "=r"(r3) : "r"(a));
}
__device__ __forceinline__ void ldsm_x2(uint32_t& r0, uint32_t& r1, uint32_t a) {
    asm volatile("ldmatrix.sync.aligned.m8n8.x2.shared.b16 {%0,%1},[%2];"
                 : "=r"(r0), "=r"(r1) : "r"(a));
}
__device__ __forceinline__ void mma_bf16(float* c, const uint32_t* a, const uint32_t* b) {
    asm volatile(
        "mma.sync.aligned.m16n8k16.row.col.f32.bf16.bf16.f32 "
        "{%0,%1,%2,%3},{%4,%5,%6,%7},{%8,%9},{%0,%1,%2,%3};"
        : "+f"(c[0]), "+f"(c[1]), "+f"(c[2]), "+f"(c[3])
        : "r"(a[0]), "r"(a[1]), "r"(a[2]), "r"(a[3]), "r"(b[0]), "r"(b[1]));
}
__device__ __forceinline__ void cp_async16(uint32_t s, const void* g) {
    asm volatile("cp.async.cg.shared.global [%0], [%1], 16;" :: "r"(s), "l"(g));
}
__device__ __forceinline__ void cp_commit() {
    asm volatile("cp.async.commit_group;");
}
template <int N> __device__ __forceinline__ void cp_wait() {
    asm volatile("cp.async.wait_group %0;" :: "n"(N));
}

// ---------------------------------------------------------------------------
// Fused prep kernel:
//   blocks [0, 512)   : convert W1,W2 fp32 -> bf16 (4 floats per thread)
//   blocks [512, 640) : LN, 8 rows per block (one warp per row)
// ---------------------------------------------------------------------------
__global__ void prep_kernel(const float* __restrict__ W1,
                            const float* __restrict__ W2,
                            const float* __restrict__ x,
                            const float* __restrict__ bp,
                            const float* __restrict__ g2,
                            const float* __restrict__ b2)
{
    if (blockIdx.x < 512) {
        const int i   = blockIdx.x * blockDim.x + threadIdx.x;
        const int idx = i * 4;
        const float* s;
        __nv_bfloat16* d;
        if (idx < Hdim * Cdim) { s = W1 + idx;                 d = g_W1 + idx; }
        else                   { s = W2 + (idx - Hdim * Cdim); d = g_W2 + (idx - Hdim * Cdim); }
        const float4 v = *reinterpret_cast<const float4*>(s);
        __nv_bfloat162 p0, p1;
        p0.x = __float2bfloat16(v.x); p0.y = __float2bfloat16(v.y);
        p1.x = __float2bfloat16(v.z); p1.y = __float2bfloat16(v.w);
        reinterpret_cast<__nv_bfloat162*>(d)[0] = p0;
        reinterpret_cast<__nv_bfloat162*>(d)[1] = p1;
        return;
    }
    // LN part: one warp per row
    const int gtid = (blockIdx.x - 512) * blockDim.x + threadIdx.x;
    const int row  = gtid >> 5;
    const int lane = gtid & 31;
    const int c0   = lane * 8;
    const float* rp = x + (size_t)row * Cdim + c0;

    float v[8];
    {
        const float4 a  = *reinterpret_cast<const float4*>(rp);
        const float4 b  = *reinterpret_cast<const float4*>(rp + 4);
        const float4 pa = *reinterpret_cast<const float4*>(bp + c0);
        const float4 pb = *reinterpret_cast<const float4*>(bp + c0 + 4);
        v[0] = a.x + pa.x; v[1] = a.y + pa.y; v[2] = a.z + pa.z; v[3] = a.w + pa.w;
        v[4] = b.x + pb.x; v[5] = b.y + pb.y; v[6] = b.z + pb.z; v[7] = b.w + pb.w;
    }
    float s = 0.f, q = 0.f;
    #pragma unroll
    for (int j = 0; j < 8; j++) { s += v[j]; q += v[j] * v[j]; }
    #pragma unroll
    for (int o = 16; o > 0; o >>= 1) {
        s += __shfl_xor_sync(0xffffffffu, s, o);
        q += __shfl_xor_sync(0xffffffffu, q, o);
    }
    const float mean = s * (1.0f / Cdim);
    const float var  = q * (1.0f / Cdim) - mean * mean;
    const float inv  = rsqrtf(var + 1e-5f);

    const float4 ga = *reinterpret_cast<const float4*>(g2 + c0);
    const float4 gb = *reinterpret_cast<const float4*>(g2 + c0 + 4);
    const float4 ba = *reinterpret_cast<const float4*>(b2 + c0);
    const float4 bb = *reinterpret_cast<const float4*>(b2 + c0 + 4);
    const float gg[8]  = {ga.x, ga.y, ga.z, ga.w, gb.x, gb.y, gb.z, gb.w};
    const float bbv[8] = {ba.x, ba.y, ba.z, ba.w, bb.x, bb.y, bb.z, bb.w};

    __nv_bfloat162 o[4];
    #pragma unroll
    for (int j = 0; j < 4; j++) {
        o[j].x = __float2bfloat16((v[2*j]   - mean) * inv * gg[2*j]   + bbv[2*j]);
        o[j].y = __float2bfloat16((v[2*j+1] - mean) * inv * gg[2*j+1] + bbv[2*j+1]);
    }
    *reinterpret_cast<uint4*>(&g_h2[(size_t)row * Cdim + c0]) =
        *reinterpret_cast<uint4*>(o);
}

// ---------------------------------------------------------------------------
// Double-buffered cp.async bf16 HMMA GEMM, 512 threads (16 warps).
//   C[m,n] = sum_k A[m,k]*B[n,k]   (A:[M,K], B:[N,K] bf16 row-major)
// Warp grid: WARPS_MxWARPS_N; warp tile WM x WN.
// MODE 0: relu(acc + bias[n]) -> bf16 Cout
// MODE 1: acc + resid[m,n] + bias[n] + bias2[n] -> fp32 Cout
// ---------------------------------------------------------------------------
template <int BM, int BN, int BK, int WARPS_M, int WARPS_N, int MODE>
__global__ void __launch_bounds__(WARPS_M * WARPS_N * 32, 1)
mma_gemm(const __nv_bfloat16* __restrict__ A,
         const __nv_bfloat16* __restrict__ B,
         void* __restrict__ Cout,
         int Ktot, int Ntot,
         const float* __restrict__ bias,
         const float* __restrict__ resid,
         const float* __restrict__ bias2)
{
    constexpr int NT  = WARPS_M * WARPS_N * 32;
    constexpr int WM  = BM / WARPS_M;
    constexpr int WN  = BN / WARPS_N;
    constexpr int LDS = BK + 8;
    constexpr int MT  = WM / 16;
    constexpr int NTt = WN / 8;

    __shared__ __nv_bfloat16 As[2][BM * LDS];
    __shared__ __nv_bfloat16 Bs[2][BN * LDS];

    const int tid  = threadIdx.x;
    const int lane = tid & 31;
    const int warp = tid >> 5;
    const int wm   = warp / WARPS_N;
    const int wn   = warp % WARPS_N;
    const int m0   = blockIdx.y * BM;
    const int n0   = blockIdx.x * BN;
    const int kIters = Ktot / BK;

    auto load_stage = [&](int buf, int k0) {
        #pragma unroll
        for (int i = tid; i < BM * BK / 8; i += NT) {
            const int r = i / (BK / 8), cv = i % (BK / 8);
            cp_async16(smem_u32(&As[buf][r * LDS + cv * 8]),
                       &A[(size_t)(m0 + r) * Ktot + k0 + cv * 8]);
        }
        #pragma unroll
        for (int i = tid; i < BN * BK / 8; i += NT) {
            const int r = i / (BK / 8), cv = i % (BK / 8);
            cp_async16(smem_u32(&Bs[buf][r * LDS + cv * 8]),
                       &B[(size_t)(n0 + r) * Ktot + k0 + cv * 8]);
        }
        cp_commit();
    };

    float acc[MT][NTt][4];
    #pragma unroll
    for (int i = 0; i < MT; i++)
        #pragma unroll
        for (int j = 0; j < NTt; j++)
            #pragma unroll
            for (int r = 0; r < 4; r++) acc[i][j][r] = 0.f;

    load_stage(0, 0);

    for (int it = 0; it < kIters; it++) {
        const int buf = it & 1;
        if (it + 1 < kIters) {
            load_stage((it + 1) & 1, (it + 1) * BK);
            cp_wait<1>();
        } else {
            cp_wait<0>();
        }
        __syncthreads();

        #pragma unroll
        for (int ks = 0; ks < BK; ks += 16) {
            uint32_t afrag[MT][4];
            #pragma unroll
            for (int mt = 0; mt < MT; mt++) {
                const int row = wm * WM + mt * 16 + (lane & 15);
                const int col = ks + (lane >> 4) * 8;
                ldsm_x4(afrag[mt][0], afrag[mt][1], afrag[mt][2], afrag[mt][3],
                        smem_u32(&As[buf][row * LDS + col]));
            }
            uint32_t bfrag[NTt][2];
            #pragma unroll
            for (int nt = 0; nt < NTt; nt++) {
                const int row = wn * WN + nt * 8 + (lane & 7);
                const int col = ks + ((lane >> 3) & 1) * 8;
                ldsm_x2(bfrag[nt][0], bfrag[nt][1],
                        smem_u32(&Bs[buf][row * LDS + col]));
            }
            #pragma unroll
            for (int mt = 0; mt < MT; mt++)
                #pragma unroll
                for (int nt = 0; nt < NTt; nt++)
                    mma_bf16(acc[mt][nt], afrag[mt], bfrag[nt]);
        }
        __syncthreads();
    }

    // Epilogue
    #pragma unroll
    for (int mt = 0; mt < MT; mt++) {
        #pragma unroll
        for (int nt = 0; nt < NTt; nt++) {
            const int m = m0 + wm * WM + mt * 16 + (lane >> 2);
            const int n = n0 + wn * WN + nt * 8 + (lane & 3) * 2;
            float c0 = acc[mt][nt][0], c1 = acc[mt][nt][1];
            float c2 = acc[mt][nt][2], c3 = acc[mt][nt][3];
            if (MODE == 0) {
                const float b0 = bias[n], b1 = bias[n + 1];
                c0 = fmaxf(c0 + b0, 0.f); c1 = fmaxf(c1 + b1, 0.f);
                c2 = fmaxf(c2 + b0, 0.f); c3 = fmaxf(c3 + b1, 0.f);
                __nv_bfloat16* O = (__nv_bfloat16*)Cout;
                __nv_bfloat162 p;
                p.x = __float2bfloat16(c0); p.y = __float2bfloat16(c1);
                *reinterpret_cast<__nv_bfloat162*>(&O[(size_t)m * Ntot + n]) = p;
                p.x = __float2bfloat16(c2); p.y = __float2bfloat16(c3);
                *reinterpret_cast<__nv_bfloat162*>(&O[(size_t)(m + 8) * Ntot + n]) = p;
            } else {
                float* O = (float*)Cout;
                const float b0 = bias[n] + bias2[n];
                const float b1 = bias[n + 1] + bias2[n + 1];
                const float2 r0 = *reinterpret_cast<const float2*>(&resid[(size_t)m * Ntot + n]);
                const float2 r1 = *reinterpret_cast<const float2*>(&resid[(size_t)(m + 8) * Ntot + n]);
                float2 p;
                p.x = c0 + r0.x + b0; p.y = c1 + r0.y + b1;
                *reinterpret_cast<float2*>(&O[(size_t)m * Ntot + n]) = p;
                p.x = c2 + r1.x + b0; p.y = c3 + r1.y + b1;
                *reinterpret_cast<float2*>(&O[(size_t)(m + 8) * Ntot + n]) = p;
            }
        }
    }
}

// ---------------------------------------------------------------------------
// Attention branch is exactly 0 (transform *= 0.0)  =>  sa == bp.
//   y = (x + bp) + relu(LN(x+bp)@W1^T + bf1) @ W2^T + bf2
// Inputs: 0:x 1:Wt 2:Wp 3:bp 4:g1 5:b1 6:g2 7:b2 8:W1 9:bf1 10:W2 11:bf2
// ---------------------------------------------------------------------------
extern "C" void kernel_launch(void* const* d_in, const int* in_sizes, int n_in,
                              void* d_out, int out_size)
{
    const float* x   = (const float*)d_in[0];
    const float* bp  = (const float*)d_in[3];
    const float* g2  = (const float*)d_in[6];
    const float* b2  = (const float*)d_in[7];
    const float* W1  = (const float*)d_in[8];
    const float* bf1 = (const float*)d_in[9];
    const float* W2  = (const float*)d_in[10];
    const float* bf2 = (const float*)d_in[11];
    float* out = (float*)d_out;

    __nv_bfloat16 *h2p, *hidp, *w1p, *w2p;
    cudaGetSymbolAddress((void**)&h2p,  g_h2);
    cudaGetSymbolAddress((void**)&hidp, g_hid);
    cudaGetSymbolAddress((void**)&w1p,  g_W1);
    cudaGetSymbolAddress((void**)&w2p,  g_W2);

    // 1) fused: convert W1,W2 -> bf16  +  LN -> bf16 h2
    prep_kernel<<<512 + 128, 256>>>(W1, W2, x, bp, g2, b2);

    // 2) hid = relu(h2 @ W1^T + bf1) : M=1024 N=1024 K=256 -> bf16
    //    512 thr, 16 warps (2x8), WM=32 WN=16, grid 8x16 = 128 blocks
    mma_gemm<64, 128, 64, 2, 8, 0>
        <<<dim3(Hdim / 128, Mrows / 64), 512>>>(
            h2p, w1p, hidp, Cdim, Hdim, bf1, nullptr, nullptr);

    // 3) out = hid @ W2^T + x + bp + bf2 : M=1024 N=256 K=1024 -> fp32
    //    512 thr, 16 warps (4x4), WM=16 WN=8, grid 8x16 = 128 blocks
    mma_gemm<64, 32, 128, 4, 4, 1>
        <<<dim3(Cdim / 32, Mrows / 64), 512>>>(
            hidp, w2p, out, Hdim, Cdim, bp, x, bf2);
}